// round 1
// baseline (speedup 1.0000x reference)
#include <cuda_runtime.h>
#include <cuda_bf16.h>
#include <cstdint>

// Problem constants
#define NB 16     // batch
#define NP 1024   // primary caps
#define NJ 32     // out caps
#define NE 64     // Dp (contraction)
#define ND 64     // D

// K1 tiling
#define JG 8      // j's per CTA
#define EC 16     // e-chunk for cp.async pipeline

// ---------------- scratch (static device allocations are the allowed path) ---
__device__ float g_u[(size_t)NB * NP * NJ * ND];       // 134 MB: u[b,p,j,d]
__device__ float g_spart[(size_t)NB * 64 * NJ * ND];   // 8 MB: per-(b,warp) partial sums
__device__ float g_vj0[NB * NJ * ND];
__device__ float g_vj1[NB * NJ * ND];
__device__ float g_bij[NB * NP * NJ];                  // routing logits

// ---------------- f32x2 helpers (packed-FMA: 2x fp32 throughput) -------------
__device__ __forceinline__ unsigned long long pack2(float x, float y) {
    unsigned long long r;
    asm("mov.b64 %0, {%1,%2};" : "=l"(r) : "f"(x), "f"(y));
    return r;
}
__device__ __forceinline__ float2 unpack2(unsigned long long v) {
    float2 r;
    asm("mov.b64 {%0,%1}, %2;" : "=f"(r.x), "=f"(r.y) : "l"(v));
    return r;
}
__device__ __forceinline__ void ffma2(unsigned long long& acc,
                                      unsigned long long a, unsigned long long b) {
    asm("fma.rn.f32x2 %0, %1, %2, %0;" : "+l"(acc) : "l"(a), "l"(b));
}
__device__ __forceinline__ void cpasync16(void* dst, const void* src) {
    uint32_t s = (uint32_t)__cvta_generic_to_shared(dst);
    asm volatile("cp.async.cg.shared.global [%0], [%1], 16;" :: "r"(s), "l"(src));
}

// =============================================================================
// K1: u[b,p,j,d] = sum_e inp[b,p,e] * W[p,j,e,d] + bias[p,j,d]
// CTA = (p, group of 8 j).  128 threads, thread tile 8b x 8d.
// W streamed through smem with cp.async double buffer (e-chunks of 16).
// =============================================================================
extern __shared__ float k1_smem[];

__global__ __launch_bounds__(128, 3) void k_gemm(const float* __restrict__ inp,
                                                 const float* __restrict__ W,
                                                 const float* __restrict__ bias) {
    float* Ws    = k1_smem;                     // [2][JG][EC][ND] = 64 KB
    float* inp_t = k1_smem + 2 * JG * EC * ND;  // [NE][NB] transposed, 4 KB

    const int p   = blockIdx.x;
    const int jg  = blockIdx.y;
    const int tid = threadIdx.x;

    // Load inp[b,p,:] for all 16 b, transposed to inp_t[e][b]
    {
        int b = tid >> 3, e0 = (tid & 7) << 3;
        const float4* src = (const float4*)(inp + ((size_t)b * NP + p) * NE + e0);
        float4 v0 = src[0], v1 = src[1];
        float v[8] = {v0.x, v0.y, v0.z, v0.w, v1.x, v1.y, v1.z, v1.w};
#pragma unroll
        for (int k = 0; k < 8; k++) inp_t[(e0 + k) * NB + b] = v[k];
    }

    const float* Wbase = W + ((size_t)p * NJ + (size_t)jg * JG) * NE * ND;

    auto prefetch = [&](int c, int buf) {
        // one chunk = JG*EC*ND floats = 32 KB = 2048 float4; 16 per thread
#pragma unroll
        for (int i = 0; i < 16; i++) {
            int ft  = i * 128 + tid;
            int j   = ft >> 8;
            int rem = ft & 255;
            int el  = rem >> 4;
            int d4  = rem & 15;
            const float* src = Wbase + ((size_t)j * NE + (c * EC + el)) * ND + d4 * 4;
            float* dst = Ws + (((size_t)buf * JG + j) * EC + el) * ND + d4 * 4;
            cpasync16(dst, src);
        }
        asm volatile("cp.async.commit_group;");
    };

    prefetch(0, 0);
    prefetch(1, 1);
    __syncthreads();  // inp_t ready

    // thread -> (j_local, b0, d0); mapping chosen so each 8-lane LDS phase
    // touches <=128B of a Ws row (conflict-free)
    const int jl = tid >> 4;
    const int r  = tid & 15;
    const int b0 = (r & 1) << 3;
    const int d0 = (r >> 1) << 3;

    unsigned long long acc[8][4];
#pragma unroll
    for (int i = 0; i < 8; i++)
#pragma unroll
        for (int k = 0; k < 4; k++) acc[i][k] = 0ull;

#pragma unroll 1
    for (int c = 0; c < 4; c++) {
        if (c < 3) asm volatile("cp.async.wait_group 1;");
        else       asm volatile("cp.async.wait_group 0;");
        __syncthreads();
        const float* wrow = Ws + (((size_t)(c & 1) * JG + jl) * EC) * ND + d0;
        const float* irow = inp_t + (size_t)(c * EC) * NB + b0;
#pragma unroll
        for (int el = 0; el < EC; el++) {
            const ulonglong2* wp = (const ulonglong2*)(wrow + (size_t)el * ND);
            ulonglong2 w0 = wp[0], w1 = wp[1];  // 8 W floats (d0..d0+7)
            float4 i0 = *(const float4*)(irow + (size_t)el * NB);
            float4 i1 = *(const float4*)(irow + (size_t)el * NB + 4);
            float ia[8] = {i0.x, i0.y, i0.z, i0.w, i1.x, i1.y, i1.z, i1.w};
#pragma unroll
            for (int bi = 0; bi < 8; bi++) {
                unsigned long long av = pack2(ia[bi], ia[bi]);
                ffma2(acc[bi][0], av, w0.x);
                ffma2(acc[bi][1], av, w0.y);
                ffma2(acc[bi][2], av, w1.x);
                ffma2(acc[bi][3], av, w1.y);
            }
        }
        __syncthreads();
        if (c + 2 < 4) prefetch(c + 2, c & 1);
    }

    // epilogue: + bias, store u
    const int j = jg * JG + jl;
    const float* bptr = bias + ((size_t)p * NJ + j) * ND + d0;
    float4 bb0 = *(const float4*)(bptr);
    float4 bb1 = *(const float4*)(bptr + 4);
#pragma unroll
    for (int bi = 0; bi < 8; bi++) {
        float2 v0 = unpack2(acc[bi][0]);
        float2 v1 = unpack2(acc[bi][1]);
        float2 v2 = unpack2(acc[bi][2]);
        float2 v3 = unpack2(acc[bi][3]);
        float* dst = g_u + ((((size_t)(b0 + bi)) * NP + p) * NJ + j) * ND + d0;
        *(float4*)dst       = make_float4(v0.x + bb0.x, v0.y + bb0.y, v1.x + bb0.z, v1.y + bb0.w);
        *(float4*)(dst + 4) = make_float4(v2.x + bb1.x, v2.y + bb1.y, v3.x + bb1.z, v3.y + bb1.w);
    }
}

// =============================================================================
// K2: partial sum over p (iteration 0 has exactly uniform c = 1/32)
// CTA = (chunk of 16 p, b).  Writes g_spart[b][chunk][2048].
// =============================================================================
__global__ void k_psum() {
    int ch = blockIdx.x;   // 64 chunks
    int b  = blockIdx.y;   // 16
    int t  = threadIdx.x;  // 256, each handles 8 contiguous elements
    float4 a0 = make_float4(0, 0, 0, 0), a1 = make_float4(0, 0, 0, 0);
    size_t base = (((size_t)b * NP) + (size_t)ch * 16) * (NJ * ND) + (size_t)t * 8;
#pragma unroll
    for (int pi = 0; pi < 16; pi++) {
        const float4* r4 = (const float4*)(g_u + base + (size_t)pi * (NJ * ND));
        float4 v0 = r4[0], v1 = r4[1];
        a0.x += v0.x; a0.y += v0.y; a0.z += v0.z; a0.w += v0.w;
        a1.x += v1.x; a1.y += v1.y; a1.z += v1.z; a1.w += v1.w;
    }
    float* dst = g_spart + ((size_t)b * 64 + ch) * (NJ * ND) + (size_t)t * 8;
    *(float4*)dst       = a0;
    *(float4*)(dst + 4) = a1;
}

// =============================================================================
// K3: reduce 64 partials + squash.  which: 0 -> g_vj0, 1 -> g_vj1, 2 -> d_out.
// grid (j, b), 32 threads (lane = d-pair).
// =============================================================================
__global__ void k_squash(float scale, int which, float* __restrict__ outext) {
    int j = blockIdx.x, b = blockIdx.y, lane = threadIdx.x;
    float* out = (which == 0) ? g_vj0 : (which == 1) ? g_vj1 : outext;
    float2 acc = make_float2(0.f, 0.f);
#pragma unroll 8
    for (int k = 0; k < 64; k++) {
        const float2 v = *(const float2*)(g_spart + (((size_t)b * 64) + k) * (NJ * ND)
                                          + (size_t)j * ND + 2 * lane);
        acc.x += v.x; acc.y += v.y;
    }
    acc.x *= scale; acc.y *= scale;
    float s2 = acc.x * acc.x + acc.y * acc.y;
#pragma unroll
    for (int off = 16; off; off >>= 1) s2 += __shfl_xor_sync(0xffffffffu, s2, off);
    float f = sqrtf(s2) / (1.0f + s2);   // x*(s2/(1+s2))/sqrt(s2) == x*sqrt(s2)/(1+s2)
    float* dst = out + ((size_t)b * NJ + j) * ND + 2 * lane;
    dst[0] = acc.x * f;
    dst[1] = acc.y * f;
}

// =============================================================================
// K4: fused routing pass.  MODE==1: bij_prev = 0, writes bij = agreement.
//     MODE==2: a = bij_prev + agreement (no write).  Then softmax over J and
//     accumulate c*u into register accumulators; flush per-warp partials.
// grid (8, b), 256 threads = 8 warps; warp handles 16 consecutive p.
// =============================================================================
template <int MODE>
__global__ __launch_bounds__(256, 1) void k_route(int which_vj) {
    __shared__ float vj_s[NJ * ND];  // 8 KB
    const float* vj_in = (which_vj == 0) ? g_vj0 : g_vj1;
    int b = blockIdx.y;
    int t = threadIdx.x;
    {
        const float4* src = (const float4*)(vj_in + (size_t)b * NJ * ND) + t * 2;
        float4 v0 = src[0], v1 = src[1];
        *(float4*)(vj_s + t * 8)     = v0;
        *(float4*)(vj_s + t * 8 + 4) = v1;
    }
    __syncthreads();

    int warp = t >> 5, lane = t & 31;
    int wIdx = blockIdx.x * 8 + warp;  // 0..63

    float sacc[NJ * 2];
#pragma unroll
    for (int i = 0; i < NJ * 2; i++) sacc[i] = 0.f;

#pragma unroll 1
    for (int pi = 0; pi < 16; pi++) {
        int p = wIdx * 16 + pi;
        const float* ubase = g_u + (((size_t)b * NP + p) * NJ) * ND + 2 * lane;
        float2 u2[NJ];
#pragma unroll
        for (int jj = 0; jj < NJ; jj++) u2[jj] = *(const float2*)(ubase + (size_t)jj * ND);

        float a[NJ];
#pragma unroll
        for (int jj = 0; jj < NJ; jj++) {
            float2 v = *(const float2*)(vj_s + jj * ND + 2 * lane);
            a[jj] = u2[jj].x * v.x + u2[jj].y * v.y;
        }
#pragma unroll
        for (int jj = 0; jj < NJ; jj++) {
#pragma unroll
            for (int off = 16; off; off >>= 1)
                a[jj] += __shfl_xor_sync(0xffffffffu, a[jj], off);
        }

        const size_t bij_off = ((size_t)b * NP + p) * NJ;
        if (MODE == 2) {
#pragma unroll
            for (int q = 0; q < 8; q++) {
                float4 bv = *(const float4*)(g_bij + bij_off + q * 4);
                a[q * 4 + 0] += bv.x; a[q * 4 + 1] += bv.y;
                a[q * 4 + 2] += bv.z; a[q * 4 + 3] += bv.w;
            }
        } else {
            if (lane == 0) {
#pragma unroll
                for (int q = 0; q < 8; q++)
                    *(float4*)(g_bij + bij_off + q * 4) =
                        make_float4(a[q * 4], a[q * 4 + 1], a[q * 4 + 2], a[q * 4 + 3]);
            }
        }

        // softmax over j (replicated in every lane; values identical post-bfly)
        float m = a[0];
#pragma unroll
        for (int jj = 1; jj < NJ; jj++) m = fmaxf(m, a[jj]);
        float s = 0.f;
#pragma unroll
        for (int jj = 0; jj < NJ; jj++) { a[jj] = __expf(a[jj] - m); s += a[jj]; }
        float inv = 1.0f / s;
#pragma unroll
        for (int jj = 0; jj < NJ; jj++) {
            float c = a[jj] * inv;
            sacc[2 * jj]     += c * u2[jj].x;
            sacc[2 * jj + 1] += c * u2[jj].y;
        }
    }

    float* dst = g_spart + ((size_t)b * 64 + wIdx) * (NJ * ND) + 2 * lane;
#pragma unroll
    for (int jj = 0; jj < NJ; jj++)
        *(float2*)(dst + (size_t)jj * ND) = make_float2(sacc[2 * jj], sacc[2 * jj + 1]);
}

// =============================================================================
extern "C" void kernel_launch(void* const* d_in, const int* in_sizes, int n_in,
                              void* d_out, int out_size) {
    const float* inp  = (const float*)d_in[0];
    const float* W    = (const float*)d_in[1];
    const float* bias = (const float*)d_in[2];
    float* out = (float*)d_out;

    const int k1_smem_bytes = (2 * JG * EC * ND + NE * NB) * (int)sizeof(float);  // 69632
    cudaFuncSetAttribute(k_gemm, cudaFuncAttributeMaxDynamicSharedMemorySize, k1_smem_bytes);

    // u = inp @ W + b
    k_gemm<<<dim3(NP, 4), 128, k1_smem_bytes>>>(inp, W, bias);
    // iteration 0: c uniform -> plain p-sum, scale 1/32, squash -> vj0
    k_psum<<<dim3(64, NB), 256>>>();
    k_squash<<<dim3(NJ, NB), 32>>>(1.0f / 32.0f, 0, out);
    // iteration 1: bij = agree(vj0); c = softmax(bij); s1 = sum c*u -> vj1
    k_route<1><<<dim3(8, NB), 256>>>(0);
    k_squash<<<dim3(NJ, NB), 32>>>(1.0f, 1, out);
    // iteration 2: c = softmax(bij + agree(vj1)); final s -> squash -> out
    k_route<2><<<dim3(8, NB), 256>>>(1);
    k_squash<<<dim3(NJ, NB), 32>>>(1.0f, 2, out);
}